// round 1
// baseline (speedup 1.0000x reference)
#include <cuda_runtime.h>
#include <cuda_bf16.h>
#include <math.h>

// Problem constants
#define HIDDEN 128
#define STATE  256
#define SEQ    4096
#define BATCH  16
#define TROWS  (BATCH * SEQ)      // 65536
#define LC     128                // scan chunk length
#define NCHUNK (SEQ / LC)         // 32 chunks per sequence
#define LOG2LC 7

// ---------------------------------------------------------------------------
// Scratch (static device globals — no allocations allowed)
// ---------------------------------------------------------------------------
__device__ float g_u [(size_t)TROWS * STATE];   // step * (x @ B^T)   [t][n]
__device__ float g_ys[(size_t)TROWS * STATE];   // scan output y_t    [t][n]
__device__ float g_Bs[STATE * HIDDEN];          // step_n * B[n][h]
__device__ float g_coef[STATE * 4];             // a,b,c,d  (M11,M12,M21,M22)
__device__ float g_mp  [STATE * 4];             // M^LC
__device__ float g_carry[(size_t)BATCH * NCHUNK * STATE * 2]; // (z,y) per chunk

// ---------------------------------------------------------------------------
// Prep: per-state coefficients, M^LC by squaring, step-scaled B
// ---------------------------------------------------------------------------
__global__ void prep_kernel(const float* __restrict__ A_diag,
                            const float* __restrict__ steps,
                            const float* __restrict__ Bw)
{
    int n = threadIdx.x;  // 256 threads
    float st   = 1.0f / (1.0f + expf(-steps[n]));
    float Av   = fmaxf(A_diag[n], 0.0f);
    float s2A  = st * st * Av;
    float schur = 1.0f / (1.0f + s2A);
    float a = 1.0f - s2A * schur;     // M11
    float b = -st * Av * schur;       // M12
    float c = st * schur;             // M21
    float d = schur;                  // M22

    g_coef[n*4+0] = a;
    g_coef[n*4+1] = b;
    g_coef[n*4+2] = c;
    g_coef[n*4+3] = d;

    // M^LC via repeated squaring (LC = 2^7)
    float pa = a, pb = b, pc = c, pd = d;
    #pragma unroll
    for (int i = 0; i < LOG2LC; i++) {
        float qa = pa*pa + pb*pc;
        float qb = pa*pb + pb*pd;
        float qc = pc*pa + pd*pc;
        float qd = pc*pb + pd*pd;
        pa = qa; pb = qb; pc = qc; pd = qd;
    }
    g_mp[n*4+0] = pa;
    g_mp[n*4+1] = pb;
    g_mp[n*4+2] = pc;
    g_mp[n*4+3] = pd;

    // Fold step into B: u = x @ (step*B)^T
    for (int h = 0; h < HIDDEN; h++)
        g_Bs[n*HIDDEN + h] = st * Bw[n*HIDDEN + h];
}

// ---------------------------------------------------------------------------
// SGEMM (NT): C[M,N] = A[M,K] @ Bm[N,K]^T    (+ optional  D[col]*x[row,col])
// BM=BN=128, BK=16, 256 threads, 8x8 per-thread tile. All dims divide evenly.
// ---------------------------------------------------------------------------
#define GBM 128
#define GBN 128
#define GBK 16
#define GTM 8
#define GTN 8

template<bool FUSE_DX>
__global__ void __launch_bounds__(256)
sgemm_nt_kernel(const float* __restrict__ A,
                const float* __restrict__ Bm,
                float* __restrict__ Cout,
                int M, int N, int K,
                const float* __restrict__ xin,
                const float* __restrict__ Dv)
{
    __shared__ float As[GBK][GBM + 4];
    __shared__ float Bs[GBK][GBN + 4];

    const int tid  = threadIdx.x;
    const int row0 = blockIdx.x * GBM;
    const int col0 = blockIdx.y * GBN;
    const int tx = tid & 15;          // 0..15 (N dir)
    const int ty = tid >> 4;          // 0..15 (M dir)

    float acc[GTM][GTN];
    #pragma unroll
    for (int i = 0; i < GTM; i++)
        #pragma unroll
        for (int j = 0; j < GTN; j++)
            acc[i][j] = 0.0f;

    for (int k0 = 0; k0 < K; k0 += GBK) {
        // Load A tile (BM x BK) transposed into As[k][m]
        #pragma unroll
        for (int it = 0; it < 2; it++) {
            int idx = tid + it * 256;          // 0..511
            int r   = idx >> 2;                // 0..127
            int k4  = idx & 3;                 // 0..3
            float4 v = *(const float4*)(A + (size_t)(row0 + r) * K + k0 + k4 * 4);
            As[k4*4+0][r] = v.x;
            As[k4*4+1][r] = v.y;
            As[k4*4+2][r] = v.z;
            As[k4*4+3][r] = v.w;
        }
        // Load B tile (BN x BK) transposed into Bs[k][n]
        #pragma unroll
        for (int it = 0; it < 2; it++) {
            int idx = tid + it * 256;
            int r   = idx >> 2;
            int k4  = idx & 3;
            float4 v = *(const float4*)(Bm + (size_t)(col0 + r) * K + k0 + k4 * 4);
            Bs[k4*4+0][r] = v.x;
            Bs[k4*4+1][r] = v.y;
            Bs[k4*4+2][r] = v.z;
            Bs[k4*4+3][r] = v.w;
        }
        __syncthreads();

        #pragma unroll
        for (int k = 0; k < GBK; k++) {
            float af[GTM], bf[GTN];
            #pragma unroll
            for (int i = 0; i < GTM; i++) af[i] = As[k][ty * GTM + i];
            #pragma unroll
            for (int j = 0; j < GTN; j++) bf[j] = Bs[k][tx * GTN + j];
            #pragma unroll
            for (int i = 0; i < GTM; i++)
                #pragma unroll
                for (int j = 0; j < GTN; j++)
                    acc[i][j] = fmaf(af[i], bf[j], acc[i][j]);
        }
        __syncthreads();
    }

    // Epilogue
    float dv[GTN];
    if (FUSE_DX) {
        #pragma unroll
        for (int j = 0; j < GTN; j++)
            dv[j] = Dv[col0 + tx * GTN + j];
    }
    #pragma unroll
    for (int i = 0; i < GTM; i++) {
        int r = row0 + ty * GTM + i;
        float* crow = Cout + (size_t)r * N + col0 + tx * GTN;
        #pragma unroll
        for (int j4 = 0; j4 < GTN / 4; j4++) {
            float4 o = make_float4(acc[i][j4*4+0], acc[i][j4*4+1],
                                   acc[i][j4*4+2], acc[i][j4*4+3]);
            if (FUSE_DX) {
                const float4 xv = *(const float4*)(xin + (size_t)r * N + col0 + tx * GTN + j4 * 4);
                o.x = fmaf(dv[j4*4+0], xv.x, o.x);
                o.y = fmaf(dv[j4*4+1], xv.y, o.y);
                o.z = fmaf(dv[j4*4+2], xv.z, o.z);
                o.w = fmaf(dv[j4*4+3], xv.w, o.w);
            }
            *(float4*)(crow + j4 * 4) = o;
        }
    }
}

// ---------------------------------------------------------------------------
// Scan phase 1: per (batch, chunk), 256 state-lanes; local scan from zero
// state, record chunk end-state. Fully coalesced 1KB loads per step.
//   z' = a*(z+u) + b*y ;  y' = c*(z+u) + d*y      (F1 = a*u, F2 = c*u)
// ---------------------------------------------------------------------------
__global__ void __launch_bounds__(256) scan_phase1_kernel()
{
    int n   = threadIdx.x;
    int blk = blockIdx.x;               // 0 .. BATCH*NCHUNK-1
    int b   = blk / NCHUNK;
    int ch  = blk % NCHUNK;

    const float4 cf = *(const float4*)&g_coef[n * 4];
    const float* up = g_u + ((size_t)b * SEQ + (size_t)ch * LC) * STATE + n;

    float z = 0.0f, y = 0.0f;
    #pragma unroll 4
    for (int i = 0; i < LC; i++) {
        float u  = up[(size_t)i * STATE];
        float zu = z + u;
        float zn = fmaf(cf.x, zu, cf.y * y);
        float yn = fmaf(cf.z, zu, cf.w * y);
        z = zn; y = yn;
    }
    ((float2*)g_carry)[(size_t)blk * STATE + n] = make_float2(z, y);
}

// ---------------------------------------------------------------------------
// Scan phase 2: per (batch, state-lane) scan across chunk end-states using
// M^LC; rewrite carry buffer in place with chunk carry-IN states.
// ---------------------------------------------------------------------------
__global__ void __launch_bounds__(256) scan_phase2_kernel()
{
    int n = threadIdx.x;
    int b = blockIdx.x;                 // 0..BATCH-1
    const float4 mp = *(const float4*)&g_mp[n * 4];

    float z = 0.0f, y = 0.0f;
    for (int c = 0; c < NCHUNK; c++) {
        size_t idx = ((size_t)b * NCHUNK + c) * STATE + n;
        float2 e = ((float2*)g_carry)[idx];        // chunk-local end state
        ((float2*)g_carry)[idx] = make_float2(z, y); // carry-in for chunk c
        float zn = fmaf(mp.x, z, fmaf(mp.y, y, e.x));
        float yn = fmaf(mp.z, z, fmaf(mp.w, y, e.y));
        z = zn; y = yn;
    }
}

// ---------------------------------------------------------------------------
// Scan phase 3: rerun each chunk from its carry-in, writing y_t to g_ys.
// ---------------------------------------------------------------------------
__global__ void __launch_bounds__(256) scan_phase3_kernel()
{
    int n   = threadIdx.x;
    int blk = blockIdx.x;
    int b   = blk / NCHUNK;
    int ch  = blk % NCHUNK;

    const float4 cf = *(const float4*)&g_coef[n * 4];
    const size_t base = ((size_t)b * SEQ + (size_t)ch * LC) * STATE + n;
    const float* up = g_u  + base;
    float*       yp = g_ys + base;

    float2 s0 = ((float2*)g_carry)[(size_t)blk * STATE + n];
    float z = s0.x, y = s0.y;

    #pragma unroll 4
    for (int i = 0; i < LC; i++) {
        float u  = up[(size_t)i * STATE];
        float zu = z + u;
        float zn = fmaf(cf.x, zu, cf.y * y);
        float yn = fmaf(cf.z, zu, cf.w * y);
        z = zn; y = yn;
        yp[(size_t)i * STATE] = y;
    }
}

// ---------------------------------------------------------------------------
// kernel_launch
// Inputs (metadata order): x[16,4096,128], A_diag[256], steps[256],
//                          B[256,128], C[128,256], D[128]
// Output: [16,4096,128] fp32
// ---------------------------------------------------------------------------
extern "C" void kernel_launch(void* const* d_in, const int* in_sizes, int n_in,
                              void* d_out, int out_size)
{
    const float* x      = (const float*)d_in[0];
    const float* A_diag = (const float*)d_in[1];
    const float* steps  = (const float*)d_in[2];
    const float* Bw     = (const float*)d_in[3];
    const float* Cw     = (const float*)d_in[4];
    const float* Dv     = (const float*)d_in[5];
    float* out = (float*)d_out;

    float *u_ptr, *ys_ptr, *bs_ptr;
    cudaGetSymbolAddress((void**)&u_ptr,  g_u);
    cudaGetSymbolAddress((void**)&ys_ptr, g_ys);
    cudaGetSymbolAddress((void**)&bs_ptr, g_Bs);

    // 1. Coefficients + step-scaled B
    prep_kernel<<<1, 256>>>(A_diag, steps, Bw);

    // 2. GEMM1: g_u = x @ (step*B)^T   [65536,128]x[256,128]^T -> [65536,256]
    {
        dim3 grid(TROWS / GBM, STATE / GBN);   // (512, 2)
        sgemm_nt_kernel<false><<<grid, 256>>>(x, bs_ptr, u_ptr,
                                              TROWS, STATE, HIDDEN,
                                              nullptr, nullptr);
    }

    // 3-5. Chunked parallel scan
    scan_phase1_kernel<<<BATCH * NCHUNK, 256>>>();
    scan_phase2_kernel<<<BATCH, 256>>>();
    scan_phase3_kernel<<<BATCH * NCHUNK, 256>>>();

    // 6. GEMM2: out = g_ys @ C^T + D*x  [65536,256]x[128,256]^T -> [65536,128]
    {
        dim3 grid(TROWS / GBM, HIDDEN / GBN);  // (512, 1)
        sgemm_nt_kernel<true><<<grid, 256>>>(ys_ptr, Cw, out,
                                             TROWS, HIDDEN, STATE,
                                             x, Dv);
    }
}

// round 3
// speedup vs baseline: 1.5928x; 1.5928x over previous
#include <cuda_runtime.h>
#include <cuda_bf16.h>
#include <math.h>
#include <stdint.h>

// Problem constants
#define HIDDEN 128
#define STATE  256
#define SEQ    4096
#define BATCH  16
#define TROWS  (BATCH * SEQ)      // 65536
#define LC     128                // scan chunk length
#define NCHUNK (SEQ / LC)         // 32 chunks per sequence
#define LOG2LC 7

// ---------------------------------------------------------------------------
// Scratch (static device globals — no allocations allowed)
// ---------------------------------------------------------------------------
__device__ float g_u [(size_t)TROWS * STATE];   // step * (x @ B^T)   [t][n]
__device__ float g_ys[(size_t)TROWS * STATE];   // scan output y_t    [t][n]
__device__ float g_coef[STATE * 4];             // a,b,c,d
__device__ float g_mp  [STATE * 4];             // M^LC
__device__ float g_step[STATE];
__device__ float g_carry[(size_t)BATCH * NCHUNK * STATE * 2];

// bf16 hi/lo split weights
__device__ __nv_bfloat16 g_B1hi[STATE * HIDDEN];  // step-scaled B
__device__ __nv_bfloat16 g_B1lo[STATE * HIDDEN];
__device__ __nv_bfloat16 g_Chi [HIDDEN * STATE];
__device__ __nv_bfloat16 g_Clo [HIDDEN * STATE];

// ---------------------------------------------------------------------------
// Helpers
// ---------------------------------------------------------------------------
__device__ __forceinline__ uint32_t smem_u32(const void* p) {
    uint32_t a;
    asm("{ .reg .u64 t; cvta.to.shared.u64 t, %1; cvt.u32.u64 %0, t; }"
        : "=r"(a) : "l"(p));
    return a;
}
__device__ __forceinline__ uint32_t pack_bf16(__nv_bfloat16 a, __nv_bfloat16 b) {
    return (uint32_t)__bfloat16_as_ushort(a) | ((uint32_t)__bfloat16_as_ushort(b) << 16);
}
__device__ __forceinline__ void split2(float v, __nv_bfloat16& h, __nv_bfloat16& l) {
    h = __float2bfloat16(v);
    l = __float2bfloat16(v - __bfloat162float(h));
}

#define LDSM_X4(r0, r1, r2, r3, addr)                                          \
    asm volatile("ldmatrix.sync.aligned.m8n8.x4.shared.b16 {%0,%1,%2,%3}, [%4];" \
        : "=r"(r0), "=r"(r1), "=r"(r2), "=r"(r3) : "r"(addr))

#define MMA_BF16(d, a, b)                                                      \
    asm volatile("mma.sync.aligned.m16n8k16.row.col.f32.bf16.bf16.f32 "        \
        "{%0,%1,%2,%3}, {%4,%5,%6,%7}, {%8,%9}, {%0,%1,%2,%3};"                \
        : "+f"((d)[0]), "+f"((d)[1]), "+f"((d)[2]), "+f"((d)[3])               \
        : "r"((a)[0]), "r"((a)[1]), "r"((a)[2]), "r"((a)[3]),                  \
          "r"((b)[0]), "r"((b)[1]))

// ---------------------------------------------------------------------------
// Prep: per-state coefficients, M^LC by squaring, step
// ---------------------------------------------------------------------------
__global__ void prep_kernel(const float* __restrict__ A_diag,
                            const float* __restrict__ steps)
{
    int n = threadIdx.x;
    float st   = 1.0f / (1.0f + expf(-steps[n]));
    float Av   = fmaxf(A_diag[n], 0.0f);
    float s2A  = st * st * Av;
    float schur = 1.0f / (1.0f + s2A);
    float a = 1.0f - s2A * schur;
    float b = -st * Av * schur;
    float c = st * schur;
    float d = schur;

    g_step[n] = st;
    g_coef[n*4+0] = a; g_coef[n*4+1] = b; g_coef[n*4+2] = c; g_coef[n*4+3] = d;

    float pa = a, pb = b, pc = c, pd = d;
    #pragma unroll
    for (int i = 0; i < LOG2LC; i++) {
        float qa = pa*pa + pb*pc;
        float qb = pa*pb + pb*pd;
        float qc = pc*pa + pd*pc;
        float qd = pc*pb + pd*pd;
        pa = qa; pb = qb; pc = qc; pd = qd;
    }
    g_mp[n*4+0] = pa; g_mp[n*4+1] = pb; g_mp[n*4+2] = pc; g_mp[n*4+3] = pd;
}

// Weight conversion: step*B and C into bf16 hi/lo
__global__ void wconv_kernel(const float* __restrict__ Bw,
                             const float* __restrict__ Cw)
{
    int idx = blockIdx.x * 256 + threadIdx.x;
    if (idx < STATE * HIDDEN) {
        int n = idx >> 7;
        float v = g_step[n] * Bw[idx];
        __nv_bfloat16 h, l; split2(v, h, l);
        g_B1hi[idx] = h; g_B1lo[idx] = l;
    } else {
        int j = idx - STATE * HIDDEN;
        __nv_bfloat16 h, l; split2(Cw[j], h, l);
        g_Chi[j] = h; g_Clo[j] = l;
    }
}

// ---------------------------------------------------------------------------
// mma.sync GEMM (NT): Cout[M,N] = A[M,KFULL] @ W[N,KFULL]^T  via bf16x3 split
// M-tile 128 per CTA, full N resident, K streamed in 128-halves.
// 8 warps in 2x4 layout; warp tile 64 x (N/4); m16n8k16 fragments.
// SMEM rows padded to 136 bf16 (272 B) -> ldmatrix conflict-free.
// ---------------------------------------------------------------------------
#define SP 136           // padded row stride in bf16 elements
#define SPB 272          // row stride in bytes
#define KH 128           // K half

template<int N, int KFULL, int KHALVES, bool FUSE_DX>
__global__ void __launch_bounds__(256, 1)
mma_gemm_kernel(const float* __restrict__ A,
                const __nv_bfloat16* __restrict__ Whi,
                const __nv_bfloat16* __restrict__ Wlo,
                float* __restrict__ Cout,
                const float* __restrict__ xin,
                const float* __restrict__ Dv)
{
    constexpr int WN = N / 4;          // warp tile N
    constexpr int MI = 4;              // 64 / 16
    constexpr int NI = WN / 8;         // n8 fragments per warp
    constexpr uint32_t SA_HI = 0;
    constexpr uint32_t SA_LO = 128u * SPB;              // 34816
    constexpr uint32_t SW_HI = 2u * 128u * SPB;         // 69632
    constexpr uint32_t SW_LO = SW_HI + (uint32_t)N * SPB;

    extern __shared__ char dsm_raw[];
    char* dsm = (char*)(((uintptr_t)dsm_raw + 1023) & ~(uintptr_t)1023);
    const uint32_t dbase = smem_u32(dsm);

    const int tid  = threadIdx.x;
    const int lane = tid & 31;
    const int w    = tid >> 5;
    const int row0 = blockIdx.x * 128;
    const int warp_m = (w & 1) * 64;
    const int warp_n = (w >> 1) * WN;

    // per-lane ldmatrix row/col offsets
    const int a_row = (lane & 7) + ((lane >> 3) & 1) * 8;
    const int a_k8  = (lane >> 4) * 8;
    const int b_row = (lane & 7) + (lane >> 4) * 8;
    const int b_k8  = ((lane >> 3) & 1) * 8;

    float acc[MI][NI][4];
    #pragma unroll
    for (int mi = 0; mi < MI; mi++)
        #pragma unroll
        for (int ni = 0; ni < NI; ni++)
            #pragma unroll
            for (int q = 0; q < 4; q++)
                acc[mi][ni][q] = 0.0f;

    for (int h = 0; h < KHALVES; h++) {
        const int kh0 = h * KH;
        __syncthreads();   // all warps done reading previous half

        // ---- stage A half: fp32 -> bf16 hi/lo into padded SMEM ----
        #pragma unroll
        for (int it = 0; it < 16; it++) {
            int idx = tid + it * 256;          // 4096 float4s
            int r   = idx >> 5;                // row 0..127
            int c4  = idx & 31;                // float4 idx in row
            int k   = c4 * 4;
            float4 v = *(const float4*)(A + (size_t)(row0 + r) * KFULL + kh0 + k);
            __nv_bfloat16 h0,l0,h1,l1,h2,l2,h3,l3;
            split2(v.x,h0,l0); split2(v.y,h1,l1); split2(v.z,h2,l2); split2(v.w,h3,l3);
            uint32_t o = (uint32_t)r * SPB + (uint32_t)k * 2;
            *(uint32_t*)(dsm + SA_HI + o)     = pack_bf16(h0, h1);
            *(uint32_t*)(dsm + SA_HI + o + 4) = pack_bf16(h2, h3);
            *(uint32_t*)(dsm + SA_LO + o)     = pack_bf16(l0, l1);
            *(uint32_t*)(dsm + SA_LO + o + 4) = pack_bf16(l2, l3);
        }
        // ---- stage W half: bf16 hi/lo (uint4 = 8 bf16) ----
        #pragma unroll
        for (int it = 0; it < N / 8; it++) {
            int idx = tid + it * 256;          // N*32 uint4 total (hi+lo)
            int half = idx / (N * 16);         // 0 = hi, 1 = lo
            int rem  = idx - half * (N * 16);
            int r    = rem >> 4;
            int k8   = (rem & 15) * 8;
            const __nv_bfloat16* src = half ? Wlo : Whi;
            uint4 v = *(const uint4*)(src + (size_t)r * KFULL + kh0 + k8);
            uint32_t o = (half ? SW_LO : SW_HI) + (uint32_t)r * SPB + (uint32_t)k8 * 2;
            *(uint4*)(dsm + o) = v;
        }
        __syncthreads();

        // ---- 3 passes: Ahi*Whi, Ahi*Wlo, Alo*Whi ----
        #pragma unroll
        for (int pass = 0; pass < 3; pass++) {
            const uint32_t Abase = dbase + (pass == 2 ? SA_LO : SA_HI);
            const uint32_t Wbase = dbase + (pass == 1 ? SW_LO : SW_HI);
            #pragma unroll
            for (int kk = 0; kk < KH / 16; kk++) {
                const int k0 = kk * 16;
                uint32_t af[MI][4];
                #pragma unroll
                for (int mi = 0; mi < MI; mi++) {
                    uint32_t addr = Abase
                        + (uint32_t)(warp_m + mi * 16 + a_row) * SPB
                        + (uint32_t)(k0 + a_k8) * 2;
                    LDSM_X4(af[mi][0], af[mi][1], af[mi][2], af[mi][3], addr);
                }
                uint32_t bf[NI][2];
                #pragma unroll
                for (int nj = 0; nj < NI / 2; nj++) {
                    uint32_t addr = Wbase
                        + (uint32_t)(warp_n + nj * 16 + b_row) * SPB
                        + (uint32_t)(k0 + b_k8) * 2;
                    uint32_t r0, r1, r2, r3;
                    LDSM_X4(r0, r1, r2, r3, addr);
                    bf[nj*2+0][0] = r0; bf[nj*2+0][1] = r1;
                    bf[nj*2+1][0] = r2; bf[nj*2+1][1] = r3;
                }
                #pragma unroll
                for (int mi = 0; mi < MI; mi++)
                    #pragma unroll
                    for (int ni = 0; ni < NI; ni++)
                        MMA_BF16(acc[mi][ni], af[mi], bf[ni]);
            }
        }
    }

    // ---- epilogue ----
    const int rbase = row0 + warp_m + (lane >> 2);
    const int cbase = warp_n + (lane & 3) * 2;
    #pragma unroll
    for (int ni = 0; ni < NI; ni++) {
        const int col = cbase + ni * 8;
        float d0 = 0.f, d1 = 0.f;
        if (FUSE_DX) { d0 = Dv[col]; d1 = Dv[col + 1]; }
        #pragma unroll
        for (int mi = 0; mi < MI; mi++) {
            const int r0 = rbase + mi * 16;
            float* p0 = Cout + (size_t)r0 * N + col;
            float* p1 = Cout + (size_t)(r0 + 8) * N + col;
            float2 o0 = make_float2(acc[mi][ni][0], acc[mi][ni][1]);
            float2 o1 = make_float2(acc[mi][ni][2], acc[mi][ni][3]);
            if (FUSE_DX) {
                const float2 x0 = *(const float2*)(xin + (size_t)r0 * N + col);
                const float2 x1 = *(const float2*)(xin + (size_t)(r0 + 8) * N + col);
                o0.x = fmaf(d0, x0.x, o0.x); o0.y = fmaf(d1, x0.y, o0.y);
                o1.x = fmaf(d0, x1.x, o1.x); o1.y = fmaf(d1, x1.y, o1.y);
            }
            *(float2*)p0 = o0;
            *(float2*)p1 = o1;
        }
    }
}

// ---------------------------------------------------------------------------
// Scan phase 1: per (batch, chunk), 256 state-lanes; local scan from zero
// ---------------------------------------------------------------------------
__global__ void __launch_bounds__(256) scan_phase1_kernel()
{
    int n   = threadIdx.x;
    int blk = blockIdx.x;
    int b   = blk / NCHUNK;
    int ch  = blk % NCHUNK;

    const float4 cf = *(const float4*)&g_coef[n * 4];
    const float* up = g_u + ((size_t)b * SEQ + (size_t)ch * LC) * STATE + n;

    float z = 0.0f, y = 0.0f;
    #pragma unroll 4
    for (int i = 0; i < LC; i++) {
        float u  = up[(size_t)i * STATE];
        float zu = z + u;
        float zn = fmaf(cf.x, zu, cf.y * y);
        float yn = fmaf(cf.z, zu, cf.w * y);
        z = zn; y = yn;
    }
    ((float2*)g_carry)[(size_t)blk * STATE + n] = make_float2(z, y);
}

// ---------------------------------------------------------------------------
// Scan phase 2: per (batch, state-lane) scan across chunk end-states (M^LC)
// ---------------------------------------------------------------------------
__global__ void __launch_bounds__(256) scan_phase2_kernel()
{
    int n = threadIdx.x;
    int b = blockIdx.x;
    const float4 mp = *(const float4*)&g_mp[n * 4];

    float z = 0.0f, y = 0.0f;
    for (int c = 0; c < NCHUNK; c++) {
        size_t idx = ((size_t)b * NCHUNK + c) * STATE + n;
        float2 e = ((float2*)g_carry)[idx];
        ((float2*)g_carry)[idx] = make_float2(z, y);
        float zn = fmaf(mp.x, z, fmaf(mp.y, y, e.x));
        float yn = fmaf(mp.z, z, fmaf(mp.w, y, e.y));
        z = zn; y = yn;
    }
}

// ---------------------------------------------------------------------------
// Scan phase 3: rerun each chunk from its carry-in, writing y_t to g_ys.
// ---------------------------------------------------------------------------
__global__ void __launch_bounds__(256) scan_phase3_kernel()
{
    int n   = threadIdx.x;
    int blk = blockIdx.x;
    int b   = blk / NCHUNK;
    int ch  = blk % NCHUNK;

    const float4 cf = *(const float4*)&g_coef[n * 4];
    const size_t base = ((size_t)b * SEQ + (size_t)ch * LC) * STATE + n;
    const float* up = g_u  + base;
    float*       yp = g_ys + base;

    float2 s0 = ((float2*)g_carry)[(size_t)blk * STATE + n];
    float z = s0.x, y = s0.y;

    #pragma unroll 4
    for (int i = 0; i < LC; i++) {
        float u  = up[(size_t)i * STATE];
        float zu = z + u;
        float zn = fmaf(cf.x, zu, cf.y * y);
        float yn = fmaf(cf.z, zu, cf.w * y);
        z = zn; y = yn;
        yp[(size_t)i * STATE] = y;
    }
}

// ---------------------------------------------------------------------------
// kernel_launch
// Inputs: x[16,4096,128], A_diag[256], steps[256], B[256,128], C[128,256], D[128]
// ---------------------------------------------------------------------------
extern "C" void kernel_launch(void* const* d_in, const int* in_sizes, int n_in,
                              void* d_out, int out_size)
{
    const float* x      = (const float*)d_in[0];
    const float* A_diag = (const float*)d_in[1];
    const float* steps  = (const float*)d_in[2];
    const float* Bw     = (const float*)d_in[3];
    const float* Cw     = (const float*)d_in[4];
    const float* Dv     = (const float*)d_in[5];
    float* out = (float*)d_out;

    float *u_ptr, *ys_ptr;
    __nv_bfloat16 *b1hi, *b1lo, *chi, *clo;
    cudaGetSymbolAddress((void**)&u_ptr,  g_u);
    cudaGetSymbolAddress((void**)&ys_ptr, g_ys);
    cudaGetSymbolAddress((void**)&b1hi,   g_B1hi);
    cudaGetSymbolAddress((void**)&b1lo,   g_B1lo);
    cudaGetSymbolAddress((void**)&chi,    g_Chi);
    cudaGetSymbolAddress((void**)&clo,    g_Clo);

    // SMEM: 1024 slack + A(2*128*272) + W(2*N*272)
    const int smem1 = 1024 + 2 * 128 * SPB + 2 * 256 * SPB;   // 209920 (N=256)
    const int smem2 = 1024 + 2 * 128 * SPB + 2 * 128 * SPB;   // 140288 (N=128)
    cudaFuncSetAttribute(mma_gemm_kernel<256, 128, 1, false>,
                         cudaFuncAttributeMaxDynamicSharedMemorySize, smem1);
    cudaFuncSetAttribute(mma_gemm_kernel<128, 256, 2, true>,
                         cudaFuncAttributeMaxDynamicSharedMemorySize, smem2);

    // 1. coefficients + weight bf16 split
    prep_kernel<<<1, 256>>>(A_diag, steps);
    wconv_kernel<<<(STATE * HIDDEN + HIDDEN * STATE) / 256, 256>>>(Bw, Cw);

    // 2. GEMM1: g_u = x @ (step*B)^T   [65536,128] x [256,128]^T
    mma_gemm_kernel<256, 128, 1, false><<<TROWS / 128, 256, smem1>>>(
        x, b1hi, b1lo, u_ptr, nullptr, nullptr);

    // 3-5. chunked parallel scan
    scan_phase1_kernel<<<BATCH * NCHUNK, 256>>>();
    scan_phase2_kernel<<<BATCH, 256>>>();
    scan_phase3_kernel<<<BATCH * NCHUNK, 256>>>();

    // 6. GEMM2: out = g_ys @ C^T + D*x   [65536,256] x [128,256]^T
    mma_gemm_kernel<128, 256, 2, true><<<TROWS / 128, 256, smem2>>>(
        ys_ptr, chi, clo, out, x, Dv);
}